// round 7
// baseline (speedup 1.0000x reference)
#include <cuda_runtime.h>

#define NNODES 40000
#define NEDGES 640000
#define TE     (NEDGES + NNODES)
#define CH     128
#define BN_EPS 1e-5f
#define NEG    0.2f
#define SCAN_BLOCKS ((NNODES + 255) / 256)

// ---------------- scratch (device globals: no allocation allowed) ----------
__device__ __align__(16) float    g_xl[NNODES * CH];
__device__ __align__(16) float    g_xr[NNODES * CH];
__device__ __align__(16) float    g_h [NNODES * CH];   // tf32-rounded bits (valid floats)
__device__ __align__(16) unsigned g_xtf[NNODES * CH];  // x pre-rounded to tf32
__device__ __align__(16) unsigned g_wtf[5 * CH * CH];  // Wl0,Wr0,Wl1,Wr1,Wlin1 tf32
__device__ __align__(16) int      g_deg[NNODES];
__device__ __align__(16) int      g_rowstart[NNODES + 4];
__device__ __align__(16) int      g_cursor[NNODES];
__device__               int      g_csr[TE];
__device__               int      g_partial[SCAN_BLOCKS + 4];

__device__ __forceinline__ unsigned f2tf(float x) {
    unsigned r;
    asm("cvt.rna.tf32.f32 %0, %1;" : "=r"(r) : "f"(x));
    return r;
}

// ---------------- pre-convert x and weights to tf32 -------------------------
__global__ void k_cvt_x(const float* __restrict__ x) {
    int i = (blockIdx.x * 256 + threadIdx.x) * 4;  // NNODES*CH = 5,120,000
    float4 v = *(const float4*)&x[i];
    uint4 t;
    t.x = f2tf(v.x); t.y = f2tf(v.y); t.z = f2tf(v.z); t.w = f2tf(v.w);
    *(uint4*)&g_xtf[i] = t;
}

__global__ void k_cvt_w(const float* __restrict__ W0, const float* __restrict__ W1,
                        const float* __restrict__ W2, const float* __restrict__ W3,
                        const float* __restrict__ W4) {
    int i = (blockIdx.x * 256 + threadIdx.x) * 4;  // 5*16384 = 81920
    int m = i >> 14, off = i & 16383;
    const float* W = (m == 0) ? W0 : (m == 1) ? W1 : (m == 2) ? W2 : (m == 3) ? W3 : W4;
    float4 v = *(const float4*)&W[off];
    uint4 t;
    t.x = f2tf(v.x); t.y = f2tf(v.y); t.z = f2tf(v.z); t.w = f2tf(v.w);
    *(uint4*)&g_wtf[i] = t;
}

// ---------------- CSR build --------------------------------------------------
__global__ void k_init_deg() {
    int i = blockIdx.x * blockDim.x + threadIdx.x;
    if (i < NNODES) g_deg[i] = 1;  // self loop
}

__global__ void k_hist(const int* __restrict__ dst) {
    int i = blockIdx.x * blockDim.x + threadIdx.x;
    if (i < NEDGES) atomicAdd(&g_deg[dst[i]], 1);
}

__global__ void k_scan1() {
    __shared__ int sm[256];
    int i = blockIdx.x * 256 + threadIdx.x;
    int v = (i < NNODES) ? g_deg[i] : 0;
    sm[threadIdx.x] = v;
    __syncthreads();
    #pragma unroll
    for (int off = 128; off; off >>= 1) {
        if (threadIdx.x < off) sm[threadIdx.x] += sm[threadIdx.x + off];
        __syncthreads();
    }
    if (threadIdx.x == 0) g_partial[blockIdx.x] = sm[0];
}

__global__ void k_scan2() {
    __shared__ int sm[256];
    int t = threadIdx.x;
    int v = (t < SCAN_BLOCKS) ? g_partial[t] : 0;
    sm[t] = v;
    __syncthreads();
    int val = v;
    #pragma unroll
    for (int off = 1; off < 256; off <<= 1) {
        int u = (t >= off) ? sm[t - off] : 0;
        __syncthreads();
        val += u;
        sm[t] = val;
        __syncthreads();
    }
    if (t < SCAN_BLOCKS) g_partial[t] = val - v;  // exclusive
}

__global__ void k_scan3() {
    __shared__ int sm[256];
    int t = threadIdx.x;
    int i = blockIdx.x * 256 + t;
    int v = (i < NNODES) ? g_deg[i] : 0;
    sm[t] = v;
    __syncthreads();
    int val = v;
    #pragma unroll
    for (int off = 1; off < 256; off <<= 1) {
        int u = (t >= off) ? sm[t - off] : 0;
        __syncthreads();
        val += u;
        sm[t] = val;
        __syncthreads();
    }
    int excl = g_partial[blockIdx.x] + val - v;
    if (i < NNODES) {
        g_rowstart[i] = excl;
        g_cursor[i]   = excl;
    }
    if (i == NNODES - 1) g_rowstart[NNODES] = excl + v;
}

__global__ void k_scatter(const int* __restrict__ ei) {
    int i = blockIdx.x * blockDim.x + threadIdx.x;
    if (i < NEDGES) {
        int s = ei[i];
        int d = ei[NEDGES + i];
        int pos = atomicAdd(&g_cursor[d], 1);
        g_csr[pos] = s;
    } else if (i < TE) {
        int node = i - NEDGES;
        int pos = atomicAdd(&g_cursor[node], 1);
        g_csr[pos] = node;
    }
}

// ---------------- TF32 tensor-core GEMM --------------------------------------
// Block tile 64x128, 4 warps, warp tile 32x64. Inputs already tf32 bits.
// blockIdx.y: 0 -> B=g_wtf[b1], C=g_xl ; 1 -> B=g_wtf[b2], C=g_xr.
// asel: 0 -> A=g_xtf, 1 -> A=(bits of) g_h (gat writes tf32-rounded values).
#define SA_STRIDE 132
#define SB_STRIDE 136
#define MM_SMEM_UINTS (64 * SA_STRIDE + 128 * SB_STRIDE)
#define MM_SMEM_BYTES (MM_SMEM_UINTS * 4)

__device__ __forceinline__ void mma_tf32(float* c, const unsigned* a,
                                         unsigned b0, unsigned b1) {
    asm volatile(
        "mma.sync.aligned.m16n8k8.row.col.f32.tf32.tf32.f32 "
        "{%0,%1,%2,%3}, {%4,%5,%6,%7}, {%8,%9}, {%0,%1,%2,%3};"
        : "+f"(c[0]), "+f"(c[1]), "+f"(c[2]), "+f"(c[3])
        : "r"(a[0]), "r"(a[1]), "r"(a[2]), "r"(a[3]), "r"(b0), "r"(b1));
}

__global__ __launch_bounds__(128) void k_mm_tc(
    int asel, int b1, const float* __restrict__ bias1,
    int b2, const float* __restrict__ bias2, int relu)
{
    extern __shared__ unsigned smem[];
    unsigned* sA = smem;                 // [64][132]
    unsigned* sB = sA + 64 * SA_STRIDE;  // [128][136]

    const unsigned* A = asel ? (const unsigned*)g_h : g_xtf;
    const unsigned* B    = g_wtf + (blockIdx.y ? b2 : b1) * (CH * CH);
    const float*    bias = blockIdx.y ? bias2 : bias1;
    float*          C    = blockIdx.y ? g_xr  : g_xl;

    const int tid = threadIdx.x;
    const int wid = tid >> 5, lane = tid & 31;
    const int q = lane & 3, g = lane >> 2;
    const int row0 = blockIdx.x * 64;
    const int mrow = (wid >> 1) * 32;    // 0 or 32
    const int colb = (wid & 1) * 64;     // 0 or 64

    // stage A (64x128): 2048 uint4 -> 16 per thread (no cvt)
    #pragma unroll
    for (int l = 0; l < 16; l++) {
        int i = tid + l * 128;
        int r = i >> 5, c = (i & 31) << 2;
        *(uint4*)&sA[r * SA_STRIDE + c] = *(const uint4*)&A[(row0 + r) * 128 + c];
    }
    // stage B (128x128): 4096 uint4 -> 32 per thread (no cvt)
    #pragma unroll
    for (int l = 0; l < 32; l++) {
        int i = tid + l * 128;
        int r = i >> 5, c = (i & 31) << 2;
        *(uint4*)&sB[r * SB_STRIDE + c] = *(const uint4*)&B[r * 128 + c];
    }
    __syncthreads();

    float acc[2][8][4];
    #pragma unroll
    for (int mt = 0; mt < 2; mt++)
        #pragma unroll
        for (int nt = 0; nt < 8; nt++)
            #pragma unroll
            for (int j = 0; j < 4; j++) acc[mt][nt][j] = 0.f;

    #pragma unroll
    for (int ks = 0; ks < 16; ks++) {
        int k0 = ks * 8;
        unsigned a[2][4];
        #pragma unroll
        for (int mt = 0; mt < 2; mt++) {
            int rb = mrow + mt * 16;
            a[mt][0] = sA[(rb + g) * SA_STRIDE + k0 + q];
            a[mt][1] = sA[(rb + 8 + g) * SA_STRIDE + k0 + q];
            a[mt][2] = sA[(rb + g) * SA_STRIDE + k0 + q + 4];
            a[mt][3] = sA[(rb + 8 + g) * SA_STRIDE + k0 + q + 4];
        }
        #pragma unroll
        for (int nt = 0; nt < 8; nt++) {
            int cb = colb + nt * 8 + g;
            unsigned b0 = sB[(k0 + q) * SB_STRIDE + cb];
            unsigned b1v = sB[(k0 + q + 4) * SB_STRIDE + cb];
            mma_tf32(acc[0][nt], a[0], b0, b1v);
            mma_tf32(acc[1][nt], a[1], b0, b1v);
        }
    }

    #pragma unroll
    for (int nt = 0; nt < 8; nt++) {
        int col = colb + nt * 8 + q * 2;
        float2 bb = *(const float2*)&bias[col];
        #pragma unroll
        for (int mt = 0; mt < 2; mt++) {
            int r0 = row0 + mrow + mt * 16 + g;
            float v0 = acc[mt][nt][0] + bb.x;
            float v1 = acc[mt][nt][1] + bb.y;
            float v2 = acc[mt][nt][2] + bb.x;
            float v3 = acc[mt][nt][3] + bb.y;
            if (relu) {
                v0 = fmaxf(v0, 0.f); v1 = fmaxf(v1, 0.f);
                v2 = fmaxf(v2, 0.f); v3 = fmaxf(v3, 0.f);
            }
            *(float2*)&C[r0 * 128 + col]       = make_float2(v0, v1);
            *(float2*)&C[(r0 + 8) * 128 + col] = make_float2(v2, v3);
        }
    }
}

// ---------------- GAT edge aggregation: one warp per destination node --------
// Output stored tf32-rounded (consumed only as GEMM A operand).
__global__ __launch_bounds__(256) void k_gat(
    const float* __restrict__ att, const float* __restrict__ bias,
    const float* __restrict__ g, const float* __restrict__ be,
    const float* __restrict__ rm, const float* __restrict__ rv)
{
    int w = (blockIdx.x * blockDim.x + threadIdx.x) >> 5;
    int lane = threadIdx.x & 31;
    if (w >= NNODES) return;
    int c0 = lane * 4;

    float4 xr4 = *(const float4*)&g_xr[w * CH + c0];
    float4 at4 = *(const float4*)&att[c0];

    int rs = g_rowstart[w];
    int re = g_rowstart[w + 1];

    float mx = __int_as_float(0xff800000);
    float ss = 0.f;
    float ax = 0.f, ay = 0.f, az = 0.f, aw = 0.f;

    for (int base = rs; base < re; base += 32) {
        int myidx = base + lane;
        int msrc = (myidx < re) ? g_csr[myidx] : 0;
        int cnt = min(32, re - base);
        for (int t = 0; t < cnt; t++) {
            int sn = __shfl_sync(0xffffffffu, msrc, t);
            float4 xl4 = *(const float4*)&g_xl[sn * CH + c0];
            float tx_ = xl4.x + xr4.x;
            float ty_ = xl4.y + xr4.y;
            float tz_ = xl4.z + xr4.z;
            float tw_ = xl4.w + xr4.w;
            tx_ = fmaxf(tx_, 0.f) + NEG * fminf(tx_, 0.f);
            ty_ = fmaxf(ty_, 0.f) + NEG * fminf(ty_, 0.f);
            tz_ = fmaxf(tz_, 0.f) + NEG * fminf(tz_, 0.f);
            tw_ = fmaxf(tw_, 0.f) + NEG * fminf(tw_, 0.f);
            float part = tx_ * at4.x + ty_ * at4.y + tz_ * at4.z + tw_ * at4.w;
            #pragma unroll
            for (int o = 16; o; o >>= 1)
                part += __shfl_xor_sync(0xffffffffu, part, o);
            float nm = fmaxf(mx, part);
            float c = __expf(mx - nm);
            float p = __expf(part - nm);
            ss = ss * c + p;
            ax = fmaf(ax, c, p * xl4.x);
            ay = fmaf(ay, c, p * xl4.y);
            az = fmaf(az, c, p * xl4.z);
            aw = fmaf(aw, c, p * xl4.w);
            mx = nm;
        }
    }

    float inv = 1.f / ss;
    float4 b4  = *(const float4*)&bias[c0];
    float4 g4  = *(const float4*)&g[c0];
    float4 be4 = *(const float4*)&be[c0];
    float4 rm4 = *(const float4*)&rm[c0];
    float4 rv4 = *(const float4*)&rv[c0];

    uint4 o;
    o.x = f2tf(fmaxf((ax * inv + b4.x - rm4.x) * (g4.x * rsqrtf(rv4.x + BN_EPS)) + be4.x, 0.f));
    o.y = f2tf(fmaxf((ay * inv + b4.y - rm4.y) * (g4.y * rsqrtf(rv4.y + BN_EPS)) + be4.y, 0.f));
    o.z = f2tf(fmaxf((az * inv + b4.z - rm4.z) * (g4.z * rsqrtf(rv4.z + BN_EPS)) + be4.z, 0.f));
    o.w = f2tf(fmaxf((aw * inv + b4.w - rm4.w) * (g4.w * rsqrtf(rv4.w + BN_EPS)) + be4.w, 0.f));
    *(uint4*)&g_h[w * CH + c0] = o;
}

// ---------------- final tiny GEMM: out[M,2] = X[M,128] @ W[128,2] + b --------
__global__ void k_lin2(const float* __restrict__ W, const float* __restrict__ b,
                       float* __restrict__ out)
{
    int w = (blockIdx.x * blockDim.x + threadIdx.x) >> 5;
    int lane = threadIdx.x & 31;
    if (w >= NNODES) return;
    float4 v  = *(const float4*)&g_xl[w * CH + lane * 4];
    float4 w0 = *(const float4*)&W[lane * 8];
    float4 w1 = *(const float4*)&W[lane * 8 + 4];
    float s0 = v.x * w0.x + v.y * w0.z + v.z * w1.x + v.w * w1.z;
    float s1 = v.x * w0.y + v.y * w0.w + v.z * w1.y + v.w * w1.w;
    #pragma unroll
    for (int o = 16; o; o >>= 1) {
        s0 += __shfl_xor_sync(0xffffffffu, s0, o);
        s1 += __shfl_xor_sync(0xffffffffu, s1, o);
    }
    if (lane == 0) {
        out[w * 2 + 0] = s0 + b[0];
        out[w * 2 + 1] = s1 + b[1];
    }
}

// ---------------- launch -----------------------------------------------------
extern "C" void kernel_launch(void* const* d_in, const int* in_sizes, int n_in,
                              void* d_out, int out_size)
{
    const float* x     = (const float*)d_in[0];
    const int*   ei    = (const int*)  d_in[1];
    const float* Wl0   = (const float*)d_in[2];
    const float* bl0   = (const float*)d_in[3];
    const float* Wr0   = (const float*)d_in[4];
    const float* br0   = (const float*)d_in[5];
    const float* att0  = (const float*)d_in[6];
    const float* bias0 = (const float*)d_in[7];
    const float* g0    = (const float*)d_in[8];
    const float* be0   = (const float*)d_in[9];
    const float* rm0   = (const float*)d_in[10];
    const float* rv0   = (const float*)d_in[11];
    const float* Wl1   = (const float*)d_in[12];
    const float* bl1   = (const float*)d_in[13];
    const float* Wr1   = (const float*)d_in[14];
    const float* br1   = (const float*)d_in[15];
    const float* att1  = (const float*)d_in[16];
    const float* bias1 = (const float*)d_in[17];
    const float* g1    = (const float*)d_in[18];
    const float* be1   = (const float*)d_in[19];
    const float* rm1   = (const float*)d_in[20];
    const float* rv1   = (const float*)d_in[21];
    const float* Wlin1 = (const float*)d_in[22];
    const float* blin1 = (const float*)d_in[23];
    const float* Wlin2 = (const float*)d_in[24];
    const float* blin2 = (const float*)d_in[25];
    float* out = (float*)d_out;

    cudaFuncSetAttribute(k_mm_tc, cudaFuncAttributeMaxDynamicSharedMemorySize,
                         MM_SMEM_BYTES);

    dim3 mm_dual(625, 2), mm_single(625, 1);
    const int GAT_BLOCKS = (NNODES * 32 + 255) / 256;  // warp per node

    k_init_deg<<<(NNODES + 255) / 256, 256>>>();                         // 1
    k_hist<<<(NEDGES + 255) / 256, 256>>>(ei + NEDGES);                  // 2
    k_cvt_w<<<80, 256>>>(Wl0, Wr0, Wl1, Wr1, Wlin1);                     // 3
    k_cvt_x<<<5000, 256>>>(x);                                           // 4
    k_mm_tc<<<mm_dual, 128, MM_SMEM_BYTES>>>(0, 0, bl0, 1, br0, 0);      // 5 (capture window)
    k_scan1<<<SCAN_BLOCKS, 256>>>();                                     // 6
    k_scan2<<<1, 256>>>();                                               // 7
    k_scan3<<<SCAN_BLOCKS, 256>>>();                                     // 8
    k_scatter<<<(TE + 255) / 256, 256>>>(ei);                            // 9

    k_gat<<<GAT_BLOCKS, 256>>>(att0, bias0, g0, be0, rm0, rv0);          // 10

    k_mm_tc<<<mm_dual, 128, MM_SMEM_BYTES>>>(1, 2, bl1, 3, br1, 0);      // 11
    k_gat<<<GAT_BLOCKS, 256>>>(att1, bias1, g1, be1, rm1, rv1);          // 12

    k_mm_tc<<<mm_single, 128, MM_SMEM_BYTES>>>(1, 4, blin1, 0, nullptr, 1); // 13
    k_lin2<<<GAT_BLOCKS, 256>>>(Wlin2, blin2, out);                      // 14
}